// round 10
// baseline (speedup 1.0000x reference)
#include <cuda_runtime.h>

typedef unsigned long long ull;

#define LOG2E_F  1.4426950408889634f
#define LOG2PI_F 1.8378770664093453f
#define LN2SQ_F  0.4804530139182014f
#define KCOMP 8
#define TPB 512
#define ELEMS_PER_BLOCK (TPB * 4)   // 2048 elements (each thread: 1 float4 = 4 elems)
#define MAGIC_F 12582912.0f         // 1.5 * 2^23 : round-to-nearest-int magic

// ---- packed f32x2 helpers ----
__device__ __forceinline__ ull pk2(float a, float b) {
    ull r; asm("mov.b64 %0, {%1, %2};" : "=l"(r) : "f"(a), "f"(b)); return r;
}
__device__ __forceinline__ void upk2(ull v, float& a, float& b) {
    asm("mov.b64 {%0, %1}, %2;" : "=f"(a), "=f"(b) : "l"(v));
}
__device__ __forceinline__ ull add2(ull a, ull b) {
    ull r; asm("add.rn.f32x2 %0, %1, %2;" : "=l"(r) : "l"(a), "l"(b)); return r;
}
__device__ __forceinline__ ull mul2(ull a, ull b) {
    ull r; asm("mul.rn.f32x2 %0, %1, %2;" : "=l"(r) : "l"(a), "l"(b)); return r;
}
__device__ __forceinline__ ull fma2(ull a, ull b, ull c) {
    ull r; asm("fma.rn.f32x2 %0, %1, %2, %3;" : "=l"(r) : "l"(a), "l"(b), "l"(c)); return r;
}
__device__ __forceinline__ float ex2f_fast(float x) {
    float r; asm("ex2.approx.ftz.f32 %0, %1;" : "=f"(r) : "f"(x)); return r;
}
__device__ __forceinline__ ull ex2_pair(ull t) {
    float t0, t1; upk2(t, t0, t1);
    return pk2(ex2f_fast(t0), ex2f_fast(t1));
}
__device__ __forceinline__ float rcpf_fast(float x) {
    float r; asm("rcp.approx.ftz.f32 %0, %1;" : "=f"(r) : "f"(x)); return r;
}

// ---- FMA-pipe exp2 for a packed pair (no MUFU) ----
// 2^t = 2^n * 2^f,  n = rni(t), f = t-n in [-0.5,0.5]
// 2^f by deg-5 Taylor (rel err ~2.4e-6); 2^n by integer bit-trick on ALU pipe.
__device__ __forceinline__ ull exp2_poly_pair(ull T,
        ull MG2, ull NMG2, ull NONE2, ull C5, ull C4, ull C3, ull C2, ull C1, ull ONE2)
{
    float t0, t1; upk2(T, t0, t1);
    t0 = fmaxf(t0, -126.0f);               // FMNMX (alu pipe): keep 2^n trick valid
    t1 = fmaxf(t1, -126.0f);
    ull Tc = pk2(t0, t1);
    ull R  = add2(Tc, MG2);                // t + magic  (low bits of each half = n)
    ull NF = add2(R, NMG2);                // n as float
    ull F  = fma2(NF, NONE2, Tc);          // f = t - n
    float r0, r1; upk2(R, r0, r1);
    unsigned s0 = (__float_as_uint(r0) + 0xB4C0007Fu) << 23;  // (n+127)<<23 (alu)
    unsigned s1 = (__float_as_uint(r1) + 0xB4C0007Fu) << 23;
    ull P = fma2(C5, F, C4);
    P = fma2(P, F, C3);
    P = fma2(P, F, C2);
    P = fma2(P, F, C1);
    P = fma2(P, F, ONE2);                  // 2^f
    ull S = pk2(__uint_as_float(s0), __uint_as_float(s1));    // 2^n
    return mul2(P, S);
}

__global__ __launch_bounds__(TPB) void gmm_hscore_kernel(
    const float4* __restrict__ x4,
    const float*  __restrict__ mean,
    const float*  __restrict__ logvar,
    const float*  __restrict__ logweight,
    float4*       __restrict__ out4)
{
    __shared__ ulonglong2 sAB[KCOMP];  // {a2, b2}
    __shared__ ulonglong2 sCV[KCOMP];  // {c2, nvs2}

    const int t = threadIdx.x;
    if (t < KCOMP) {
        float lv = logvar[t];
        float mu = mean[t];
        float lw = logweight[t];
        float iv = ex2f_fast(-lv * LOG2E_F);           // 1/var
        float a  = -0.5f * iv * LOG2E_F;
        float b  = -2.0f * a * mu;
        float c  = fmaf(a, mu * mu, (lw - 0.5f * (lv + LOG2PI_F)) * LOG2E_F);
        float nvs = -iv * (1.0f / LN2SQ_F);
        sAB[t] = make_ulonglong2(pk2(a, a), pk2(b, b));
        sCV[t] = make_ulonglong2(pk2(c, c), pk2(nvs, nvs));
    }
    __syncthreads();

    const int base = blockIdx.x * TPB + t;   // float4 index
    float4 xa = x4[base];
    ull X0 = pk2(xa.x, xa.y);
    ull X1 = pk2(xa.z, xa.w);

    const ull Z = pk2(0.0f, 0.0f);
    ull MP0 = Z, MP1 = Z, MD0 = Z, MD1 = Z, DD0 = Z, DD1 = Z;

    // Warp specialization: SMSP = wid%4. Warps 12..15 land one-per-SMSP and
    // compute exp2 on the FMA pipe; warps 0..11 (3 per SMSP) use MUFU EX2.
    // => every SMSP sees a 3:1 MUFU:poly exp mix.
    const bool use_poly = (t >> 5) >= 12;

    if (!use_poly) {
        #pragma unroll
        for (int k = 0; k < KCOMP; k++) {
            const ulonglong2 ab = sAB[k];
            const ulonglong2 cv = sCV[k];
            const ull a2 = ab.x, b2 = ab.y, c2 = cv.x, v2 = cv.y;
            ull H0 = fma2(a2, X0, b2);
            ull H1 = fma2(a2, X1, b2);
            ull T0 = fma2(H0, X0, c2);
            ull T1 = fma2(H1, X1, c2);
            ull P0 = ex2_pair(T0);
            ull P1 = ex2_pair(T1);
            ull S0 = fma2(a2, X0, H0);
            ull S1 = fma2(a2, X1, H1);
            MP0 = add2(MP0, P0);  MP1 = add2(MP1, P1);
            MD0 = fma2(P0, S0, MD0);  MD1 = fma2(P1, S1, MD1);
            ull U0 = fma2(S0, S0, v2);
            ull U1 = fma2(S1, S1, v2);
            DD0 = fma2(P0, U0, DD0);  DD1 = fma2(P1, U1, DD1);
        }
    } else {
        const ull MG2   = pk2(MAGIC_F, MAGIC_F);
        const ull NMG2  = pk2(-MAGIC_F, -MAGIC_F);
        const ull NONE2 = pk2(-1.0f, -1.0f);
        const ull ONE2  = pk2(1.0f, 1.0f);
        const ull C1 = pk2(0.69314718f, 0.69314718f);
        const ull C2 = pk2(0.24022651f, 0.24022651f);
        const ull C3 = pk2(0.05550411f, 0.05550411f);
        const ull C4 = pk2(0.00961804f, 0.00961804f);
        const ull C5 = pk2(0.00133336f, 0.00133336f);
        #pragma unroll
        for (int k = 0; k < KCOMP; k++) {
            const ulonglong2 ab = sAB[k];
            const ulonglong2 cv = sCV[k];
            const ull a2 = ab.x, b2 = ab.y, c2 = cv.x, v2 = cv.y;
            ull H0 = fma2(a2, X0, b2);
            ull H1 = fma2(a2, X1, b2);
            ull T0 = fma2(H0, X0, c2);
            ull T1 = fma2(H1, X1, c2);
            ull P0 = exp2_poly_pair(T0, MG2, NMG2, NONE2, C5, C4, C3, C2, C1, ONE2);
            ull P1 = exp2_poly_pair(T1, MG2, NMG2, NONE2, C5, C4, C3, C2, C1, ONE2);
            ull S0 = fma2(a2, X0, H0);
            ull S1 = fma2(a2, X1, H1);
            MP0 = add2(MP0, P0);  MP1 = add2(MP1, P1);
            MD0 = fma2(P0, S0, MD0);  MD1 = fma2(P1, S1, MD1);
            ull U0 = fma2(S0, S0, v2);
            ull U1 = fma2(S1, S1, v2);
            DD0 = fma2(P0, U0, DD0);  DD1 = fma2(P1, U1, DD1);
        }
    }

    // ---- epilogue: h = ln2^2 * ( -0.5*(md'/mp)^2 + dd'/mp ) ----
    float h0, h1, h2, h3;
    {
        float mp0, mp1, md0, md1, dd0, dd1;
        upk2(MP0, mp0, mp1); upk2(MD0, md0, md1); upk2(DD0, dd0, dd1);
        float r0 = rcpf_fast(mp0), r1 = rcpf_fast(mp1);
        float dl0 = md0 * r0,      dl1 = md1 * r1;
        h0 = LN2SQ_F * fmaf(-0.5f * dl0, dl0, dd0 * r0);
        h1 = LN2SQ_F * fmaf(-0.5f * dl1, dl1, dd1 * r1);
        upk2(MP1, mp0, mp1); upk2(MD1, md0, md1); upk2(DD1, dd0, dd1);
        r0 = rcpf_fast(mp0); r1 = rcpf_fast(mp1);
        dl0 = md0 * r0;      dl1 = md1 * r1;
        h2 = LN2SQ_F * fmaf(-0.5f * dl0, dl0, dd0 * r0);
        h3 = LN2SQ_F * fmaf(-0.5f * dl1, dl1, dd1 * r1);
    }

    out4[base] = make_float4(h0, h1, h2, h3);
}

extern "C" void kernel_launch(void* const* d_in, const int* in_sizes, int n_in,
                              void* d_out, int out_size) {
    const float4* x4        = (const float4*)d_in[0];
    const float*  mean      = (const float*)d_in[1];
    const float*  logvar    = (const float*)d_in[2];
    const float*  logweight = (const float*)d_in[3];
    float4*       out4      = (float4*)d_out;

    int n = in_sizes[0];                       // 4194304 = 2048 * ELEMS_PER_BLOCK
    int blocks = n / ELEMS_PER_BLOCK;          // 2048
    gmm_hscore_kernel<<<blocks, TPB>>>(x4, mean, logvar, logweight, out4);
}